// round 11
// baseline (speedup 1.0000x reference)
#include <cuda_runtime.h>
#include <math.h>

#define NTOK 512
#define CD   2048
#define HD   1024
#define HSD  2048
#define NE   8

// ---------------- scratch (static device globals: allocation-free) ----------
__device__ int   g_cnt[NE];
__device__ int   g_list[NE][NTOK];   // token index per expert-local row
__device__ float g_wl [NE][NTOK];    // softmax gate weight per row
__device__ int   g_pr [NE][NTOK];    // pair id (2*t + slot) per row
__device__ float g_sg [NTOK];        // sigmoid shared-expert gate
__device__ float g_G  [NE][NTOK*HD]; // routed gate pre-act
__device__ float g_U  [NE][NTOK*HD]; // routed up pre-act
__device__ float g_Hb [NE][NTOK*HD]; // silu(g)*u
__device__ float g_R  [2*NTOK][CD];  // routed output per pair (scaled)
__device__ float g_SG [NTOK*HSD];
__device__ float g_SU [NTOK*HSD];
__device__ float g_SY [NTOK*HSD];
__device__ float g_SS [NTOK*CD];

typedef unsigned long long u64;

__device__ __forceinline__ u64 pack2(float x, float y) {
    u64 d; asm("mov.b64 %0,{%1,%2};" : "=l"(d) : "f"(x), "f"(y)); return d;
}
__device__ __forceinline__ void unpack2(u64 v, float& lo, float& hi) {
    asm("mov.b64 {%0,%1},%2;" : "=f"(lo), "=f"(hi) : "l"(v));
}
// Blackwell packed fp32x2 FMA — 2x fp32 throughput vs scalar FFMA (PTX-only path)
__device__ __forceinline__ void ffma2(u64& c, u64 a, u64 b) {
    asm("fma.rn.f32x2 %0,%1,%2,%0;" : "+l"(c) : "l"(a), "l"(b));
}

// ---------------- tiny kernels ----------------------------------------------
__global__ void k_zero() { if (threadIdx.x < NE) g_cnt[threadIdx.x] = 0; }

__global__ void k_route(const float* __restrict__ x,
                        const float* __restrict__ gw,
                        const float* __restrict__ seg) {
    int t = blockIdx.x, tid = threadIdx.x;
    float acc[9];
    #pragma unroll
    for (int j = 0; j < 9; j++) acc[j] = 0.f;
    const float* xr = x + (size_t)t * CD;
    for (int k = tid; k < CD; k += 256) {
        float xv = xr[k];
        #pragma unroll
        for (int j = 0; j < 8; j++) acc[j] += xv * gw[j * CD + k];
        acc[8] += xv * seg[k];
    }
    __shared__ float rb[256];
    __shared__ float sc[9];
    for (int j = 0; j < 9; j++) {
        rb[tid] = acc[j]; __syncthreads();
        for (int s = 128; s > 0; s >>= 1) {
            if (tid < s) rb[tid] += rb[tid + s];
            __syncthreads();
        }
        if (tid == 0) sc[j] = rb[0];
        __syncthreads();
    }
    if (tid == 0) {
        int e0 = 0; float b0 = sc[0];
        #pragma unroll
        for (int i = 1; i < 8; i++) if (sc[i] > b0) { b0 = sc[i]; e0 = i; }
        int e1 = -1; float b1 = -3.0e38f;
        #pragma unroll
        for (int i = 0; i < 8; i++) {
            if (i == e0) continue;
            if (sc[i] > b1) { b1 = sc[i]; e1 = i; }
        }
        float z1 = expf(b1 - b0);       // b1 <= b0 -> stable softmax over top-2
        float inv = 1.f / (1.f + z1);
        float w0 = inv, w1 = z1 * inv;
        g_sg[t] = 1.f / (1.f + expf(-sc[8]));
        int p0 = atomicAdd(&g_cnt[e0], 1);
        g_list[e0][p0] = t; g_wl[e0][p0] = w0; g_pr[e0][p0] = 2 * t;
        int p1 = atomicAdd(&g_cnt[e1], 1);
        g_list[e1][p1] = t; g_wl[e1][p1] = w1; g_pr[e1][p1] = 2 * t + 1;
    }
}

__global__ void k_silu(const float* __restrict__ g, const float* __restrict__ u,
                       float* __restrict__ y, int n) {
    int i = blockIdx.x * 256 + threadIdx.x;
    if (i < n) {
        float gv = g[i];
        y[i] = (gv / (1.f + expf(-gv))) * u[i];
    }
}

__global__ void k_combine(float* __restrict__ out, const float* __restrict__ ss) {
    int i = blockIdx.x * 256 + threadIdx.x;
    int t = i >> 11, c = i & (CD - 1);
    out[i] = g_R[2 * t][c] + g_R[2 * t + 1][c] + g_sg[t] * ss[i];
}

// ---------------- NT GEMM: C[M][N] = A[M][K] @ B[N][K]^T --------------------
// MODE 0: plain (M = 512, A row r = r, store C)
// MODE 1: gather rows of A=x via g_list[e], M = g_cnt[e], B/C offset by expert
// MODE 2: A = g_Hb[e], M = g_cnt[e], epilogue scales by g_wl and scatters to g_R[g_pr]
constexpr int BM = 128, BN = 64, BK = 16;

template <int MODE>
__global__ void __launch_bounds__(256, 2)
k_gemm(const float* __restrict__ Ag, const float* __restrict__ Bg,
       float* __restrict__ Cg, int N, int K, int aPerE, int bPerE, int cPerE) {
    __shared__ __align__(16) float As[BK][BM + 2];  // transposed, +2 pad (even, 8B-ok)
    __shared__ __align__(16) float Bs[BK][BN + 4];  // transposed, +4 pad (16B-ok)

    const int e = (MODE == 0) ? 0 : blockIdx.z;
    const int M = (MODE == 0) ? NTOK : g_cnt[e];
    const int mBase = blockIdx.y * BM;
    if (mBase >= M) return;
    const int nBase = blockIdx.x * BN;

    const float* Abase = Ag + (size_t)e * aPerE;
    const float* Bbase = Bg + (size_t)e * bPerE + (size_t)nBase * K;

    const int tid = threadIdx.x;
    const int lrow = tid >> 2;          // 0..63
    const int lkq  = (tid & 3) * 4;     // k-offset 0,4,8,12

    // A loader: 2 slots (rows lrow, lrow+64); gather/guard resolved once
    const float* aptr[2];
    #pragma unroll
    for (int l = 0; l < 2; l++) {
        int gr = mBase + lrow + l * 64;
        int srow;
        if (MODE == 1) srow = (gr < M) ? g_list[e][gr] : 0;  // OOB rows -> dummy row 0
        else           srow = gr;                            // always < 512 (valid scratch)
        aptr[l] = Abase + (size_t)srow * K + lkq;
    }
    const float* bptr = Bbase + (size_t)lrow * K + lkq;

    const int tn = tid & 15, tm = tid >> 4;
    const int n0 = tn * 4, m0 = tm * 8;

    u64 acc[16];
    #pragma unroll
    for (int i = 0; i < 16; i++) acc[i] = 0ull;

    // register-staged prefetch of tile 0
    float4 sa0 = *(const float4*)(aptr[0]);
    float4 sa1 = *(const float4*)(aptr[1]);
    float4 sb  = *(const float4*)(bptr);

    for (int k0 = 0; k0 < K; k0 += BK) {
        // commit staged tile to smem (transposed)
        As[lkq + 0][lrow] = sa0.x; As[lkq + 1][lrow] = sa0.y;
        As[lkq + 2][lrow] = sa0.z; As[lkq + 3][lrow] = sa0.w;
        As[lkq + 0][lrow + 64] = sa1.x; As[lkq + 1][lrow + 64] = sa1.y;
        As[lkq + 2][lrow + 64] = sa1.z; As[lkq + 3][lrow + 64] = sa1.w;
        Bs[lkq + 0][lrow] = sb.x; Bs[lkq + 1][lrow] = sb.y;
        Bs[lkq + 2][lrow] = sb.z; Bs[lkq + 3][lrow] = sb.w;
        __syncthreads();

        // issue next-tile global loads; completion overlaps the FFMA2 loop
        if (k0 + BK < K) {
            sa0 = *(const float4*)(aptr[0] + k0 + BK);
            sa1 = *(const float4*)(aptr[1] + k0 + BK);
            sb  = *(const float4*)(bptr    + k0 + BK);
        }

        #pragma unroll
        for (int kk = 0; kk < BK; kk++) {
            u64 a[4];
            #pragma unroll
            for (int mp = 0; mp < 4; mp++)
                a[mp] = *(const u64*)&As[kk][m0 + 2 * mp];   // natural (row, row+1) pair
            float4 bq = *(const float4*)&Bs[kk][n0];
            u64 b[4];
            b[0] = pack2(bq.x, bq.x); b[1] = pack2(bq.y, bq.y);
            b[2] = pack2(bq.z, bq.z); b[3] = pack2(bq.w, bq.w);
            #pragma unroll
            for (int mp = 0; mp < 4; mp++) {
                #pragma unroll
                for (int j = 0; j < 4; j++)
                    ffma2(acc[mp * 4 + j], a[mp], b[j]);
            }
        }
        __syncthreads();
    }

    // epilogue
    #pragma unroll
    for (int mp = 0; mp < 4; mp++) {
        int r0 = mBase + m0 + 2 * mp;
        float lo[4], hi[4];
        #pragma unroll
        for (int j = 0; j < 4; j++) unpack2(acc[mp * 4 + j], lo[j], hi[j]);
        if (MODE == 2) {
            if (r0 < M) {
                float w = g_wl[e][r0]; int p = g_pr[e][r0];
                *(float4*)&g_R[p][nBase + n0] =
                    make_float4(w * lo[0], w * lo[1], w * lo[2], w * lo[3]);
            }
            if (r0 + 1 < M) {
                float w = g_wl[e][r0 + 1]; int p = g_pr[e][r0 + 1];
                *(float4*)&g_R[p][nBase + n0] =
                    make_float4(w * hi[0], w * hi[1], w * hi[2], w * hi[3]);
            }
        } else {
            float* Cp = Cg + (size_t)e * cPerE;
            if (r0 < M)
                *(float4*)&Cp[(size_t)r0 * N + nBase + n0] =
                    make_float4(lo[0], lo[1], lo[2], lo[3]);
            if (r0 + 1 < M)
                *(float4*)&Cp[(size_t)(r0 + 1) * N + nBase + n0] =
                    make_float4(hi[0], hi[1], hi[2], hi[3]);
        }
    }
}

// ---------------- launch -----------------------------------------------------
extern "C" void kernel_launch(void* const* d_in, const int* in_sizes, int n_in,
                              void* d_out, int out_size) {
    const float* x   = (const float*)d_in[0];
    const float* gw  = (const float*)d_in[1];
    const float* wg  = (const float*)d_in[2];
    const float* wu  = (const float*)d_in[3];
    const float* wd  = (const float*)d_in[4];
    const float* shg = (const float*)d_in[5];
    const float* shu = (const float*)d_in[6];
    const float* shd = (const float*)d_in[7];
    const float* seg = (const float*)d_in[8];
    float* out = (float*)d_out;

    float *pSG, *pSU, *pSY, *pSS, *pG, *pU, *pH;
    cudaGetSymbolAddress((void**)&pSG, g_SG);
    cudaGetSymbolAddress((void**)&pSU, g_SU);
    cudaGetSymbolAddress((void**)&pSY, g_SY);
    cudaGetSymbolAddress((void**)&pSS, g_SS);
    cudaGetSymbolAddress((void**)&pG,  g_G);
    cudaGetSymbolAddress((void**)&pU,  g_U);
    cudaGetSymbolAddress((void**)&pH,  g_Hb);

    k_zero<<<1, 32>>>();
    k_route<<<NTOK, 256>>>(x, gw, seg);

    // shared expert: gate, up, silu*up, down
    dim3 gs(HSD / BN, NTOK / BM, 1);
    k_gemm<0><<<gs, 256>>>(x, shg, pSG, HSD, CD, 0, 0, 0);
    k_gemm<0><<<gs, 256>>>(x, shu, pSU, HSD, CD, 0, 0, 0);
    k_silu<<<(NTOK * HSD) / 256, 256>>>(pSG, pSU, pSY, NTOK * HSD);
    dim3 gsd(CD / BN, NTOK / BM, 1);
    k_gemm<0><<<gsd, 256>>>(pSY, shd, pSS, CD, HSD, 0, 0, 0);

    // routed experts (grouped): gate, up, silu*up, down(+scale+scatter)
    dim3 gr1(HD / BN, NTOK / BM, NE);
    k_gemm<1><<<gr1, 256>>>(x, wg, pG, HD, CD, 0, HD * CD, NTOK * HD);
    k_gemm<1><<<gr1, 256>>>(x, wu, pU, HD, CD, 0, HD * CD, NTOK * HD);
    k_silu<<<(NE * NTOK * HD) / 256, 256>>>(pG, pU, pH, NE * NTOK * HD);
    dim3 gr2(CD / BN, NTOK / BM, NE);
    k_gemm<2><<<gr2, 256>>>(pH, wd, (float*)0, CD, HD, NTOK * HD, CD * HD, 0);

    k_combine<<<(NTOK * CD) / 256, 256>>>(out, pSS);
}